// round 17
// baseline (speedup 1.0000x reference)
#include <cuda_runtime.h>

// NoTradeRegionRNN: D=2 channel RNN scan, T timesteps, B independent lanes.
// x, returns: (D, T, B) row-major. output: (D, T, B) then hT (D, 1, B).
//
// R17 = R16's 4-way parallel-in-time schedule (warmup 32, uniform 152-step
// chunks) with TWO adjacent lanes per thread. R16 is LSU-issue-bound
// (~71.5K cyc/SM of LDGSTS+LDS+STG issue vs ~59K wall), which also caps
// DRAM at 71%. Lane-pairing halves LSU instruction count per lane:
// LDS.64 smem reads, STG.64 output writes, 2x cp16 per thread per step.
// 32-thread CTAs (one warp, fully self-contained for cp.async.wait_group),
// 1024 CTAs -> 6-7 per SM, balanced. Earlier ILP2 attempts (R4/R9) lost
// because the binder then was scheduler coverage; now it is LSU issue.
// Schedule:
//   chunk0: s=0,   store chunk-steps  0..151 (global   0..151)
//   chunk1: s=120, store chunk-steps 32..151 (global 152..271)
//   chunk2: s=240, store chunk-steps 32..151 (global 272..391)
//   chunk3: s=359, store chunk-steps 33..151 (global 392..510, +hT)

__device__ __forceinline__ float relu_(float v) { return fmaxf(v, 0.0f); }
__device__ __forceinline__ float clamp_(float v, float lo, float hi) {
    return fminf(fmaxf(v, lo), hi);
}
__device__ __forceinline__ float frcp_(float v) {
    float r; asm("rcp.approx.f32 %0, %1;" : "=f"(r) : "f"(v)); return r;
}
__device__ __forceinline__ void cp16_(unsigned dst, const void* src) {
    asm volatile("cp.async.cg.shared.global [%0], [%1], 16;" :: "r"(dst), "l"(src));
}
__device__ __forceinline__ void cp_commit_() {
    asm volatile("cp.async.commit_group;");
}
template <int N>
__device__ __forceinline__ void cp_wait_() {
    asm volatile("cp.async.wait_group %0;" :: "n"(N));
}

// ---------------- parameter derivation ----------------
struct Params {
    float ac, bd;
    float Wi0, Wi1, Wh0, Wh1, W10, W11, W20, W21;
    float C_lbx, LO_lbx, HI_lbx;   // val = clamp(fma(a, slope, C), LO, HI)
    float C_ubx, LO_ubx, HI_ubx;
    float C_lby, LO_lby, HI_lby;
    float C_uby, LO_uby, HI_uby;
};

__device__ __forceinline__ Params make_params(
    const float* __restrict__ tgt, const float* __restrict__ wi,
    const float* __restrict__ wh,  const float* __restrict__ bh,
    const float* __restrict__ w1,  const float* __restrict__ w2,
    const float* __restrict__ wr)
{
    Params P;
    const float wr00 = wr[0], wr01 = wr[1], wr10 = wr[2], wr11 = wr[3];
    const float bh0 = bh[0], bh1 = bh[1];
    const float t0 = tgt[0], t1 = tgt[1];
    P.Wi0 = wi[0]; P.Wi1 = wi[1];
    P.Wh0 = wh[0]; P.Wh1 = wh[1];
    P.W10 = w1[0]; P.W11 = w1[1];
    P.W20 = w2[0]; P.W21 = w2[1];
    P.ac = wr10 / wr00;
    P.bd = wr01 / wr11;

    // Corners: k0:(-,-) k1:(-,+) k2:(+,+) k3:(+,-) applied to (bh0, bh1)
    float Cx[4], Cy[4];
    const float s0[4] = {-1.f, -1.f, 1.f, 1.f};
    const float s1[4] = {-1.f,  1.f, 1.f, -1.f};
#pragma unroll
    for (int k = 0; k < 4; ++k) {
        float vx = s0[k] * bh0, vy = s1[k] * bh1;
        Cx[k] = wr00 * vx + wr01 * vy + t0;
        Cy[k] = wr10 * vx + wr11 * vy + t1;
    }
    const bool bdp = (P.bd >= 0.0f);
    const bool acp = (P.ac >= 0.0f);
    // bound: w=(a-c)*slope; val = o - relu(A - relu(w)) == clamp(w+o-A, o-A, o)
    {
        float c = bdp ? Cy[0] : Cy[1], A = fabsf(Cx[1] - Cx[0]), o = bdp ? Cx[1] : Cx[0];
        P.C_lbx = -c * P.bd + o - A; P.LO_lbx = o - A; P.HI_lbx = o;
    }
    {
        float c = bdp ? Cy[3] : Cy[2], A = fabsf(Cx[2] - Cx[3]), o = bdp ? Cx[2] : Cx[3];
        P.C_ubx = -c * P.bd + o - A; P.LO_ubx = o - A; P.HI_ubx = o;
    }
    {
        float c = acp ? Cx[0] : Cx[3], A = fabsf(Cy[0] - Cy[3]), o = acp ? Cy[3] : Cy[0];
        P.C_lby = -c * P.ac + o - A; P.LO_lby = o - A; P.HI_lby = o;
    }
    {
        float c = acp ? Cx[1] : Cx[2], A = fabsf(Cy[1] - Cy[2]), o = acp ? Cy[2] : Cy[1];
        P.C_uby = -c * P.ac + o - A; P.LO_uby = o - A; P.HI_uby = o;
    }
    return P;
}

__device__ __forceinline__ void ntr_step(const Params& P,
                                         float& hx, float& hy,
                                         float rx, float ry,
                                         float xx, float xy)
{
    float denom = fmaf(hx, rx, fmaf(hy, ry, 1.0f));
    float inv = frcp_(denom);
    float ax = fmaf(hx, rx, hx) * inv;      // hx*(1+rx)/denom
    float ay = fmaf(hy, ry, hy) * inv;

    float lbx = clamp_(fmaf(ay, P.bd, P.C_lbx), P.LO_lbx, P.HI_lbx);
    float ubx = clamp_(fmaf(ay, P.bd, P.C_ubx), P.LO_ubx, P.HI_ubx);
    float lby = clamp_(fmaf(ax, P.ac, P.C_lby), P.LO_lby, P.HI_lby);
    float uby = clamp_(fmaf(ax, P.ac, P.C_uby), P.LO_uby, P.HI_uby);

    float g1x = relu_(fmaf(P.Wi0, xx, fmaf(P.Wh0, ax, -lbx)));
    float g1y = relu_(fmaf(P.Wi1, xy, fmaf(P.Wh1, ay, -lby)));
    float g2x = relu_(fmaf(P.W10, g1x, ubx - lbx));
    float g2y = relu_(fmaf(P.W11, g1y, uby - lby));
    hx = fmaf(P.W20, g2x, ubx);
    hy = fmaf(P.W21, g2y, uby);
}

// two independent scalar chains for a lane pair held as float2
__device__ __forceinline__ void ntr_step2(const Params& P,
                                          float2& hx, float2& hy,
                                          float2 r0, float2 r1,
                                          float2 x0, float2 x1)
{
    ntr_step(P, hx.x, hy.x, r0.x, r1.x, x0.x, x1.x);
    ntr_step(P, hx.y, hy.y, r0.y, r1.y, x0.y, x1.y);
}

// ---------------- 4-way time-split ILP2 cp.async ring (T=512, B=16384) ----
// 32-thread CTA = 1 warp covering 64 lanes (2 per thread). Stage (1024 B):
// plane p at [p*256, +256) = 64 lanes' floats. cp side: thread m with
// p = m>>3, sub = m&7 copies 16B chunks covering lanes [sub*4,+4) and
// [32+sub*4,+4) of plane p (2 x cp16 per step). Compute side: thread m
// owns lanes (2m, 2m+1) -> 4 x LDS.64 per step, conflict-free.
// Planes: 0 r0(t=s), 1 r1, 2 x0(t=s+1), 3 x1. Ring S=16 = G=4 groups x C=4.
// Every chunk: exactly NSTEPS=152 steps = NGRP=38 groups; M=34 main iters.
template <int T, int B>
__global__ void __launch_bounds__(32)
ntr_rnn_tsplit4i2(const float* __restrict__ x,
                  const float* __restrict__ ret,
                  const float* __restrict__ tgt,
                  const float* __restrict__ wi,
                  const float* __restrict__ wh,
                  const float* __restrict__ bh,
                  const float* __restrict__ w1,
                  const float* __restrict__ w2,
                  const float* __restrict__ wr,
                  float* __restrict__ out,
                  int write_hT)
{
    constexpr int S = 16;                    // ring stages (16 KB)
    constexpr int C = 4;                     // steps per commit-group
    constexpr int G = S / C;                 // 4 groups in ring
    constexpr int NGRP = 38;                 // groups per chunk (152 steps)
    constexpr int M = NGRP - G;              // 34 main iterations
    constexpr unsigned SB = 1024u;           // stage bytes (64 lanes x 4 planes)
    constexpr unsigned SF = 256u;            // stage floats
    constexpr int B2 = B / 2;                // float2 stride per timestep

    __shared__ __align__(16) float smem[S * SF];     // 16 KB

    const int m = threadIdx.x;               // 0..31
    const int chunk = blockIdx.x >> 8;       // 0..3 (256 tiles per chunk)
    const int tile = blockIdx.x & 255;
    const int gp = tile * 32 + m;            // lane-pair id (float2 index)
    const Params P = make_params(tgt, wi, wh, bh, w1, w2, wr);

    const size_t TB = (size_t)T * (size_t)B;
    const size_t TB2 = (size_t)T * (size_t)B2;

    // schedule: s_begin = {0,120,240,359}; store_from = {0,32,32,33};
    //           store_len = {152,120,120,119}
    const int s_begin    = (chunk == 3) ? 359 : 120 * chunk;
    const int store_from = (chunk == 0) ? 0 : ((chunk == 3) ? 33 : 32);
    const unsigned store_len = (chunk == 0) ? 152u : ((chunk == 3) ? 119u : 120u);

    // ---- cp.async source/dest for THIS thread (2 x 16B per step) ----
    const int p = m >> 3;
    const int sub = m & 7;
    const float* plane_base =
        (p == 0) ? ret :
        (p == 1) ? ret + TB :
        (p == 2) ? x + B :
                   x + TB + B;
    const float* cp_src = plane_base + (size_t)s_begin * B
                        + (size_t)tile * 64 + sub * 4;   // chunk A; B at +32

    const unsigned smem_base = (unsigned)__cvta_generic_to_shared(smem);
    const unsigned cpdA = smem_base + (unsigned)(p * 256 + sub * 16);
    // compute-side float2 views: plane pp of lane pair m at stage stg
#define STAGE_VAL2(stgF, pp) (*(const float2*)&smem[(stgF) + (pp) * 64 + 2 * m])

    // output pointers (float2); chunk step s writes t = s_begin + s + 1
    float2* po0 = (float2*)out + (size_t)(s_begin + 1) * B2 + gp;
    float2* po1 = (float2*)out + TB2 + (size_t)(s_begin + 1) * B2 + gp;

    // initial state: h = x[:, s_begin, :] (exact h0 for chunk 0;
    // contraction-warmup guess otherwise)
    float2 hx = __ldg((const float2*)x + (size_t)s_begin * B2 + gp);
    float2 hy = __ldg((const float2*)x + TB2 + (size_t)s_begin * B2 + gp);
    if (chunk == 0) {
        ((float2*)out)[gp] = hx;             // t = 0 plane
        ((float2*)out)[TB2 + gp] = hy;
    }

    // ---- prologue: issue groups 0..G-2, one commit each ----
#pragma unroll
    for (int gq = 0; gq < G - 1; ++gq) {
#pragma unroll
        for (int j = 0; j < C; ++j) {
            cp16_(cpdA + (unsigned)(gq * C + j) * SB,
                  cp_src + (size_t)(gq * C + j) * B);
            cp16_(cpdA + 128u + (unsigned)(gq * C + j) * SB,
                  cp_src + (size_t)(gq * C + j) * B + 32);
        }
        cp_commit_();
    }
    cp_wait_<G - 2>();               // group 0 landed

    unsigned issoff = (G - 1) * C * SB;      // byte slot of next group to issue
    unsigned ldsoff = 0;                     // float slot of next group to compute
    int stepc = 0;                           // chunk-relative step of group base

    // ---- main loop: iteration i computes group i, issues group i+G-1 ----
    for (int i = 0; i < M; ++i) {
#pragma unroll
        for (int j = 0; j < C; ++j) {
            cp16_(cpdA + issoff + (unsigned)j * SB,
                  cp_src + (size_t)(C * (G - 1) + j) * B);
            cp16_(cpdA + 128u + issoff + (unsigned)j * SB,
                  cp_src + (size_t)(C * (G - 1) + j) * B + 32);
        }
        cp_commit_();
#pragma unroll
        for (int j = 0; j < C; ++j) {
            const unsigned sf = ldsoff + j * SF;
            float2 r0 = STAGE_VAL2(sf, 0);
            float2 r1 = STAGE_VAL2(sf, 1);
            float2 x0 = STAGE_VAL2(sf, 2);
            float2 x1 = STAGE_VAL2(sf, 3);
            ntr_step2(P, hx, hy, r0, r1, x0, x1);
            if ((unsigned)(stepc + j - store_from) < store_len) {
                __stcs(po0 + (size_t)j * B2, hx);
                __stcs(po1 + (size_t)j * B2, hy);
            }
        }
        cp_wait_<G - 2>();
        cp_src += (size_t)C * B;
        po0 += (size_t)C * B2; po1 += (size_t)C * B2;
        stepc += C;
        issoff += C * SB; if (issoff == S * SB) issoff = 0;
        ldsoff += C * SF; if (ldsoff == S * SF) ldsoff = 0;
    }

    // ---- post-loop: issue final group (NGRP-1), drain, compute last G groups ----
#pragma unroll
    for (int j = 0; j < C; ++j) {
        cp16_(cpdA + issoff + (unsigned)j * SB,
              cp_src + (size_t)(C * (G - 1) + j) * B);
        cp16_(cpdA + 128u + issoff + (unsigned)j * SB,
              cp_src + (size_t)(C * (G - 1) + j) * B + 32);
    }
    cp_commit_();
    cp_wait_<0>();
#pragma unroll
    for (int gq = 0; gq < G; ++gq) {
#pragma unroll
        for (int j = 0; j < C; ++j) {
            const unsigned sf = ldsoff + j * SF;
            float2 r0 = STAGE_VAL2(sf, 0);
            float2 r1 = STAGE_VAL2(sf, 1);
            float2 x0 = STAGE_VAL2(sf, 2);
            float2 x1 = STAGE_VAL2(sf, 3);
            ntr_step2(P, hx, hy, r0, r1, x0, x1);
            if ((unsigned)(stepc + j - store_from) < store_len) {
                __stcs(po0 + (size_t)j * B2, hx);
                __stcs(po1 + (size_t)j * B2, hy);
            }
        }
        po0 += (size_t)C * B2; po1 += (size_t)C * B2;
        stepc += C;
        ldsoff += C * SF; if (ldsoff == S * SF) ldsoff = 0;
    }
#undef STAGE_VAL2

    // chunk 3 ends at global step 510 (359 + 151) -> its state is h(T).
    if (chunk == 3 && write_hT) {
        ((float2*)out)[2 * TB2 + gp] = hx;
        ((float2*)out)[2 * TB2 + B2 + gp] = hy;
    }
}

// ---------------- generic fallback (any T, B) ----------------
__global__ void __launch_bounds__(128)
ntr_rnn_generic(const float* __restrict__ x,
                const float* __restrict__ ret,
                const float* __restrict__ tgt,
                const float* __restrict__ wi,
                const float* __restrict__ wh,
                const float* __restrict__ bh,
                const float* __restrict__ w1,
                const float* __restrict__ w2,
                const float* __restrict__ wr,
                float* __restrict__ out,
                int T, int B, int write_hT)
{
    const int b = blockIdx.x * blockDim.x + threadIdx.x;
    if (b >= B) return;
    const Params P = make_params(tgt, wi, wh, bh, w1, w2, wr);

    const size_t TB = (size_t)T * (size_t)B;
    const float* r0 = ret + b;
    const float* r1 = ret + TB + b;
    const float* x0 = x + b;
    const float* x1 = x + TB + b;
    float* o0 = out + b;
    float* o1 = out + TB + b;

    float hx = __ldg(x0);
    float hy = __ldg(x1);
    o0[0] = hx; o1[0] = hy;

    for (int t = 1; t < T; ++t) {
        size_t offp = (size_t)(t - 1) * B;
        size_t offt = (size_t)t * B;
        float rx = __ldcs(r0 + offp), ry = __ldcs(r1 + offp);
        float xx = __ldcs(x0 + offt), xy = __ldcs(x1 + offt);
        ntr_step(P, hx, hy, rx, ry, xx, xy);
        __stcs(o0 + offt, hx);
        __stcs(o1 + offt, hy);
    }
    if (write_hT) {
        out[2 * TB + b] = hx;
        out[2 * TB + B + b] = hy;
    }
}

extern "C" void kernel_launch(void* const* d_in, const int* in_sizes, int n_in,
                              void* d_out, int out_size)
{
    // 0 input (D,T,B), 1 target, 2 returns (D,T,B), 3 hidden (D,1,B),
    // 4 w_input, 5 w_hidden, 6 b_hidden, 7 w_fc1, 8 w_fc2, 9 w_rotate
    const float* x   = (const float*)d_in[0];
    const float* tgt = (const float*)d_in[1];
    const float* ret = (const float*)d_in[2];
    const float* wi  = (const float*)d_in[4];
    const float* wh  = (const float*)d_in[5];
    const float* bh  = (const float*)d_in[6];
    const float* w1  = (const float*)d_in[7];
    const float* w2  = (const float*)d_in[8];
    const float* wr  = (const float*)d_in[9];
    float* out = (float*)d_out;

    const int D = 2;
    const int B = in_sizes[3] / D;
    const int T = in_sizes[0] / (D * B);
    const int write_hT = (out_size >= D * T * B + D * B) ? 1 : 0;

    constexpr int TS = 512, BS = 16384;
    if (T == TS && B == BS) {
        const int threads = 32;                      // 1 warp per CTA
        const int blocks = 4 * (BS / 64);            // 1024 CTAs: 256 per chunk
        ntr_rnn_tsplit4i2<TS, BS><<<blocks, threads>>>(
            x, ret, tgt, wi, wh, bh, w1, w2, wr, out, write_hT);
    } else {
        const int threads = 128;
        const int blocks = (B + threads - 1) / threads;
        ntr_rnn_generic<<<blocks, threads>>>(
            x, ret, tgt, wi, wh, bh, w1, w2, wr, out, T, B, write_hT);
    }
}